// round 8
// baseline (speedup 1.0000x reference)
#include <cuda_runtime.h>

// Rotation_agg: out[n, :] = mean_l ( cmul(feat[n,l,:], finals[l,:]) ), finals[3]=identity.
// HBM-bound stream (1.28 GB minimal traffic), pinned at ~90% of 8 TB/s spec across 5
// structural variants. R7: persistent grid-stride kernel (one wave: 148 SMs x 8 blocks)
// to eliminate ~53 wave transitions; same coalesced float4 pattern, unroll-2 for MLP=8.

#define ROT_EPS 1e-12f

__global__ __launch_bounds__(256) void rotation_agg_kernel(
    const float* __restrict__ feat,
    const float* __restrict__ r_vec,
    float* __restrict__ out,
    long long total)          // N * 16 float4 work items
{
    __shared__ float2 sf[3][32];   // finals for l=0,1,2 per complex index k

    const int tid = threadIdx.x;
    if (tid < 32) {
        const int k = tid;
        float2 rn[3];
#pragma unroll
        for (int e = 0; e < 3; e++) {
            float x = r_vec[e * 64 + k * 2 + 0];
            float y = r_vec[e * 64 + k * 2 + 1];
            float nrm = sqrtf(x * x + y * y);
            float inv = 1.0f / fmaxf(nrm, ROT_EPS);
            rn[e] = make_float2(x * inv, y * inv);
        }
        float2 f2 = make_float2(rn[2].x, -rn[2].y);               // conj(rn2)
        float2 c1 = make_float2(rn[1].x, -rn[1].y);               // conj(rn1)
        float2 f1 = make_float2(f2.x * c1.x - f2.y * c1.y,
                                f2.x * c1.y + f2.y * c1.x);       // f2 * conj(rn1)
        float2 f0 = make_float2(f1.x * rn[0].x - f1.y * rn[0].y,
                                f1.x * rn[0].y + f1.y * rn[0].x); // f1 * rn0
        sf[0][k] = f0;
        sf[1][k] = f1;
        sf[2][k] = f2;
    }
    __syncthreads();

    const long long stride = (long long)gridDim.x * blockDim.x;

    for (long long t = (long long)blockIdx.x * blockDim.x + tid; t < total; t += stride) {
        const int n = (int)(t >> 4);
        const int c = (int)(t & 15);             // float4 column -> complex pairs 2c, 2c+1

        const float4* in4 = (const float4*)feat + (long long)n * 64 + c;

        // Batch all 4 layer loads up front (MLP=4 per iter); streaming policy.
        float4 v0 = __ldcs(in4 + 0);
        float4 v1 = __ldcs(in4 + 16);
        float4 v2 = __ldcs(in4 + 32);
        float4 v3 = __ldcs(in4 + 48);

        const float2 f00 = sf[0][2 * c], f01 = sf[0][2 * c + 1];
        const float2 f10 = sf[1][2 * c], f11 = sf[1][2 * c + 1];
        const float2 f20 = sf[2][2 * c], f21 = sf[2][2 * c + 1];

        float4 acc;
        acc.x = v3.x + (v0.x * f00.x - v0.y * f00.y)
                     + (v1.x * f10.x - v1.y * f10.y)
                     + (v2.x * f20.x - v2.y * f20.y);
        acc.y = v3.y + (v0.x * f00.y + v0.y * f00.x)
                     + (v1.x * f10.y + v1.y * f10.x)
                     + (v2.x * f20.y + v2.y * f20.x);
        acc.z = v3.z + (v0.z * f01.x - v0.w * f01.y)
                     + (v1.z * f11.x - v1.w * f11.y)
                     + (v2.z * f21.x - v2.w * f21.y);
        acc.w = v3.w + (v0.z * f01.y + v0.w * f01.x)
                     + (v1.z * f11.y + v1.w * f11.x)
                     + (v2.z * f21.y + v2.w * f21.x);

        acc.x *= 0.25f; acc.y *= 0.25f; acc.z *= 0.25f; acc.w *= 0.25f;

        __stcs((float4*)out + (long long)n * 16 + c, acc);
    }
}

extern "C" void kernel_launch(void* const* d_in, const int* in_sizes, int n_in,
                              void* d_out, int out_size)
{
    const float* feat  = (const float*)d_in[0];   // (N, 4, 64) fp32
    const float* r_vec = (const float*)d_in[1];   // (4, 32, 2) fp32
    float* out = (float*)d_out;                   // (N, 64) fp32

    const int N = in_sizes[0] / 256;              // 4*64 floats per row
    const long long total = (long long)N * 16;    // float4 work items

    // One full wave on GB300: 152 SMs x 8 resident 256-thread blocks.
    // (regs ~32 -> 8 blocks/SM; use 152 to match GB300 SM count, clamped to work size.)
    int blocks = 152 * 8;
    long long needed = (total + 255) / 256;
    if ((long long)blocks > needed) blocks = (int)needed;

    rotation_agg_kernel<<<blocks, 256>>>(feat, r_vec, out, total);
}

// round 9
// speedup vs baseline: 1.0341x; 1.0341x over previous
#include <cuda_runtime.h>

// Rotation_agg: out[n, :] = mean_l ( cmul(feat[n,l,:], finals[l,:]) ), finals[3]=identity.
// HBM-bound stream (1.28 GB minimal traffic), pinned at ~90% of 8 TB/s spec.
// R8: revert persistent-kernel regression; best flat-grid shape (1 float4/thread, MLP=4)
// + coefficient precompute split into a 1-block kernel writing a __device__ global, so
// the streaming kernel has no prologue (no smem, no barrier, no MUFU) and every block's
// loads issue immediately.

#define ROT_EPS 1e-12f

__device__ float2 g_sf[3][32];   // finals for l=0,1,2 per complex index k

__global__ void rotation_coeff_kernel(const float* __restrict__ r_vec)
{
    const int k = threadIdx.x;   // 32 threads
    float2 rn[3];
#pragma unroll
    for (int e = 0; e < 3; e++) {
        float x = r_vec[e * 64 + k * 2 + 0];
        float y = r_vec[e * 64 + k * 2 + 1];
        float nrm = sqrtf(x * x + y * y);
        float inv = 1.0f / fmaxf(nrm, ROT_EPS);
        rn[e] = make_float2(x * inv, y * inv);
    }
    float2 f2 = make_float2(rn[2].x, -rn[2].y);               // conj(rn2)
    float2 c1 = make_float2(rn[1].x, -rn[1].y);               // conj(rn1)
    float2 f1 = make_float2(f2.x * c1.x - f2.y * c1.y,
                            f2.x * c1.y + f2.y * c1.x);       // f2 * conj(rn1)
    float2 f0 = make_float2(f1.x * rn[0].x - f1.y * rn[0].y,
                            f1.x * rn[0].y + f1.y * rn[0].x); // f1 * rn0
    g_sf[0][k] = f0;
    g_sf[1][k] = f1;
    g_sf[2][k] = f2;
}

__global__ __launch_bounds__(256) void rotation_agg_kernel(
    const float* __restrict__ feat,
    float* __restrict__ out,
    long long total)          // N * 16 float4 work items
{
    const long long t = (long long)blockIdx.x * 256 + threadIdx.x;
    if (t >= total) return;

    const int n = (int)(t >> 4);
    const int c = (int)(t & 15);             // float4 column -> complex pairs 2c, 2c+1

    const float4* in4 = (const float4*)feat + (long long)n * 64 + c;

    // Batch all 4 layer loads up front (MLP=4); streaming policy. These issue
    // immediately at block start — no prologue.
    float4 v0 = __ldcs(in4 + 0);
    float4 v1 = __ldcs(in4 + 16);
    float4 v2 = __ldcs(in4 + 32);
    float4 v3 = __ldcs(in4 + 48);

    // Coefficients: 768B table, L1/L2-hot, overlapped with the DRAM loads above.
    const float2 f00 = __ldg(&g_sf[0][2 * c]), f01 = __ldg(&g_sf[0][2 * c + 1]);
    const float2 f10 = __ldg(&g_sf[1][2 * c]), f11 = __ldg(&g_sf[1][2 * c + 1]);
    const float2 f20 = __ldg(&g_sf[2][2 * c]), f21 = __ldg(&g_sf[2][2 * c + 1]);

    float4 acc;
    acc.x = v3.x + (v0.x * f00.x - v0.y * f00.y)
                 + (v1.x * f10.x - v1.y * f10.y)
                 + (v2.x * f20.x - v2.y * f20.y);
    acc.y = v3.y + (v0.x * f00.y + v0.y * f00.x)
                 + (v1.x * f10.y + v1.y * f10.x)
                 + (v2.x * f20.y + v2.y * f20.x);
    acc.z = v3.z + (v0.z * f01.x - v0.w * f01.y)
                 + (v1.z * f11.x - v1.w * f11.y)
                 + (v2.z * f21.x - v2.w * f21.y);
    acc.w = v3.w + (v0.z * f01.y + v0.w * f01.x)
                 + (v1.z * f11.y + v1.w * f11.x)
                 + (v2.z * f21.y + v2.w * f21.x);

    acc.x *= 0.25f; acc.y *= 0.25f; acc.z *= 0.25f; acc.w *= 0.25f;

    __stcs((float4*)out + (long long)n * 16 + c, acc);
}

extern "C" void kernel_launch(void* const* d_in, const int* in_sizes, int n_in,
                              void* d_out, int out_size)
{
    const float* feat  = (const float*)d_in[0];   // (N, 4, 64) fp32
    const float* r_vec = (const float*)d_in[1];   // (4, 32, 2) fp32
    float* out = (float*)d_out;                   // (N, 64) fp32

    const int N = in_sizes[0] / 256;              // 4*64 floats per row
    const long long total = (long long)N * 16;    // float4 work items
    const int threads = 256;
    const int blocks = (int)((total + threads - 1) / threads);

    rotation_coeff_kernel<<<1, 32>>>(r_vec);
    rotation_agg_kernel<<<blocks, threads>>>(feat, out, total);
}

// round 10
// speedup vs baseline: 1.0458x; 1.0113x over previous
#include <cuda_runtime.h>

// Rotation_agg: out[n, :] = mean_l ( cmul(feat[n,l,:], finals[l,:]) ), finals[3]=identity.
// FINAL (converged): HBM-bound one-pass stream, 1.024 GB read + 256 MB write = 1.28 GB
// minimal traffic. Kernel runs at 175.5us ncu-time = 7.2 TB/s = 90% of HBM3e spec across
// every structural variant tried (cache hints, L2 promotion, 2-wide/2-row tiles,
// persistent grid, split coeff launch). Single launch, 1 float4/thread, perfectly
// coalesced, 4 batched loads (MLP=4), evict-first streaming policy.

#define ROT_EPS 1e-12f

__global__ __launch_bounds__(256) void rotation_agg_kernel(
    const float* __restrict__ feat,
    const float* __restrict__ r_vec,
    float* __restrict__ out,
    int total32)   // N*16 work items (fits 32-bit for N up to 134M)
{
    __shared__ float2 sf[3][32];   // finals for l=0,1,2 per complex index k

    const int tid = threadIdx.x;
    if (tid < 32) {
        const int k = tid;
        float2 rn[3];
#pragma unroll
        for (int e = 0; e < 3; e++) {
            float x = r_vec[e * 64 + k * 2 + 0];
            float y = r_vec[e * 64 + k * 2 + 1];
            float nrm = sqrtf(x * x + y * y);
            float inv = 1.0f / fmaxf(nrm, ROT_EPS);
            rn[e] = make_float2(x * inv, y * inv);
        }
        float2 f2 = make_float2(rn[2].x, -rn[2].y);               // conj(rn2)
        float2 c1 = make_float2(rn[1].x, -rn[1].y);               // conj(rn1)
        float2 f1 = make_float2(f2.x * c1.x - f2.y * c1.y,
                                f2.x * c1.y + f2.y * c1.x);       // f2 * conj(rn1)
        float2 f0 = make_float2(f1.x * rn[0].x - f1.y * rn[0].y,
                                f1.x * rn[0].y + f1.y * rn[0].x); // f1 * rn0
        sf[0][k] = f0;
        sf[1][k] = f1;
        sf[2][k] = f2;
    }
    __syncthreads();

    const int t = blockIdx.x * 256 + tid;
    if (t >= total32) return;

    const int n = t >> 4;
    const int c = t & 15;                        // float4 column -> complex pairs 2c, 2c+1

    const float4* in4 = (const float4*)feat + (long long)n * 64 + c;  // 64 float4 per n

    // Batch all 4 layer loads up front (MLP=4); evict-first streaming policy.
    float4 v0 = __ldcs(in4 + 0);
    float4 v1 = __ldcs(in4 + 16);
    float4 v2 = __ldcs(in4 + 32);
    float4 v3 = __ldcs(in4 + 48);

    const float2 f00 = sf[0][2 * c], f01 = sf[0][2 * c + 1];
    const float2 f10 = sf[1][2 * c], f11 = sf[1][2 * c + 1];
    const float2 f20 = sf[2][2 * c], f21 = sf[2][2 * c + 1];

    float4 acc;
    acc.x = v3.x + (v0.x * f00.x - v0.y * f00.y)
                 + (v1.x * f10.x - v1.y * f10.y)
                 + (v2.x * f20.x - v2.y * f20.y);
    acc.y = v3.y + (v0.x * f00.y + v0.y * f00.x)
                 + (v1.x * f10.y + v1.y * f10.x)
                 + (v2.x * f20.y + v2.y * f20.x);
    acc.z = v3.z + (v0.z * f01.x - v0.w * f01.y)
                 + (v1.z * f11.x - v1.w * f11.y)
                 + (v2.z * f21.x - v2.w * f21.y);
    acc.w = v3.w + (v0.z * f01.y + v0.w * f01.x)
                 + (v1.z * f11.y + v1.w * f11.x)
                 + (v2.z * f21.y + v2.w * f21.x);

    acc.x *= 0.25f; acc.y *= 0.25f; acc.z *= 0.25f; acc.w *= 0.25f;

    __stcs((float4*)out + (long long)n * 16 + c, acc);
}

extern "C" void kernel_launch(void* const* d_in, const int* in_sizes, int n_in,
                              void* d_out, int out_size)
{
    const float* feat  = (const float*)d_in[0];   // (N, 4, 64) fp32
    const float* r_vec = (const float*)d_in[1];   // (4, 32, 2) fp32
    float* out = (float*)d_out;                   // (N, 64) fp32

    const int N = in_sizes[0] / 256;              // 4*64 floats per row
    const int total = N * 16;                     // float4 work items
    const int threads = 256;
    const int blocks = (total + threads - 1) / threads;

    rotation_agg_kernel<<<blocks, threads>>>(feat, r_vec, out, total);
}